// round 3
// baseline (speedup 1.0000x reference)
#include <cuda_runtime.h>
#include <math.h>

// Problem constants
#define BATCH 2
#define SEQ   2048
#define EMB   2048
#define NH    16
#define HD    128          // head dim
#define QKV_N (3*EMB)      // 6144
#define MROWS (BATCH*SEQ)  // 4096

// ---------------------------------------------------------------------------
// Scratch (static __device__ arrays: allocation-free per harness rules)
// ---------------------------------------------------------------------------
__device__ float g_qkv[(size_t)BATCH*SEQ*QKV_N];  // 100.7 MB
__device__ float g_att[(size_t)BATCH*SEQ*EMB];    // 33.6 MB

// ---------------------------------------------------------------------------
// SGEMM: C[M,N] = A[M,K] * B[K,N], all row-major fp32.
// 128x128 block tile, BK=16, 256 threads, 8x8 register microtile.
// ---------------------------------------------------------------------------
template<int BM, int BN, int BK, int TM, int TN>
__global__ __launch_bounds__(256, 2)
void sgemm_kernel(const float* __restrict__ A, const float* __restrict__ B,
                  float* __restrict__ C, int M, int N, int K)
{
    __shared__ float As[BK][BM];   // transposed A tile
    __shared__ float Bs[BK][BN];

    const int tid = threadIdx.x;            // 0..255
    const int tx  = tid % (BN / TN);        // 0..15
    const int ty  = tid / (BN / TN);        // 0..15
    const int rowBase = blockIdx.y * BM;
    const int colBase = blockIdx.x * BN;

    float acc[TM][TN];
    #pragma unroll
    for (int i = 0; i < TM; i++)
        #pragma unroll
        for (int j = 0; j < TN; j++) acc[i][j] = 0.f;

    for (int k0 = 0; k0 < K; k0 += BK) {
        // ---- load A tile (BM x BK = 128x16): 512 float4, 2 per thread.
        // e = tid + i*256 -> consecutive lanes read consecutive 16B (coalesced).
        #pragma unroll
        for (int i = 0; i < 2; i++) {
            int e  = tid + i * 256;          // 0..511
            int r  = e >> 2;                 // 0..127
            int c4 = e & 3;                  // 0..3
            float4 v = *reinterpret_cast<const float4*>(
                &A[(size_t)(rowBase + r) * K + k0 + c4 * 4]);
            As[c4*4+0][r] = v.x;
            As[c4*4+1][r] = v.y;
            As[c4*4+2][r] = v.z;
            As[c4*4+3][r] = v.w;
        }
        // ---- load B tile (BK x BN = 16x128): 512 float4, 2 per thread.
        #pragma unroll
        for (int i = 0; i < 2; i++) {
            int e  = tid + i * 256;
            int r  = e >> 5;                 // 0..15
            int c4 = e & 31;                 // 0..31
            float4 v = *reinterpret_cast<const float4*>(
                &B[(size_t)(k0 + r) * N + colBase + c4 * 4]);
            *reinterpret_cast<float4*>(&Bs[r][c4 * 4]) = v;
        }
        __syncthreads();

        #pragma unroll
        for (int k = 0; k < BK; k++) {
            float a_reg[TM], b_reg[TN];
            #pragma unroll
            for (int i = 0; i < TM; i += 4) {
                float4 v = *reinterpret_cast<const float4*>(&As[k][ty * TM + i]);
                a_reg[i+0] = v.x; a_reg[i+1] = v.y; a_reg[i+2] = v.z; a_reg[i+3] = v.w;
            }
            #pragma unroll
            for (int j = 0; j < TN; j += 4) {
                float4 v = *reinterpret_cast<const float4*>(&Bs[k][tx * TN + j]);
                b_reg[j+0] = v.x; b_reg[j+1] = v.y; b_reg[j+2] = v.z; b_reg[j+3] = v.w;
            }
            #pragma unroll
            for (int i = 0; i < TM; i++)
                #pragma unroll
                for (int j = 0; j < TN; j++)
                    acc[i][j] += a_reg[i] * b_reg[j];
        }
        __syncthreads();
    }

    #pragma unroll
    for (int i = 0; i < TM; i++) {
        float* cp = &C[(size_t)(rowBase + ty * TM + i) * N + colBase + tx * TN];
        #pragma unroll
        for (int j = 0; j < TN; j += 4) {
            float4 v = make_float4(acc[i][j], acc[i][j+1], acc[i][j+2], acc[i][j+3]);
            *reinterpret_cast<float4*>(&cp[j]) = v;
        }
    }
}

// ---------------------------------------------------------------------------
// RoPE: rotate interleaved pairs within each head of q and k, in place.
// freqs_cis layout: [S][D/2][2] = (cos, sin)
// ---------------------------------------------------------------------------
__global__ void rope_kernel(float* __restrict__ qkv, const float* __restrict__ fc)
{
    int idx = blockIdx.x * blockDim.x + threadIdx.x;
    const int total = BATCH * SEQ * 2 * NH * (HD / 2);
    if (idx >= total) return;

    int p  = idx & (HD/2 - 1);       // 0..63
    int t  = idx >> 6;
    int h2 = t & (2*NH - 1);         // 0..31: [0,NH) = q heads, [NH,2NH) = k heads
    t >>= 5;
    int s  = t & (SEQ - 1);
    int b  = t >> 11;

    float c  = fc[(s * (HD/2) + p) * 2 + 0];
    float sn = fc[(s * (HD/2) + p) * 2 + 1];

    size_t off = (size_t)(b * SEQ + s) * QKV_N + 2 * p;
    off += (h2 < NH) ? (size_t)h2 * HD : (size_t)EMB + (size_t)(h2 - NH) * HD;

    float x0 = qkv[off], x1 = qkv[off + 1];
    qkv[off]     = x0 * c - x1 * sn;
    qkv[off + 1] = x1 * c + x0 * sn;
}

// ---------------------------------------------------------------------------
// Flash-style causal attention. One block per (q-tile of 64, b*h).
// 256 threads: tx=tid%16, ty=tid/16.
//   scores: thread owns q-rows ty*4+i (i<4), k-rows tx+16*j (j<4)
//   output: thread owns q-rows ty*4+i, cols tx*8+j (j<8)
// ---------------------------------------------------------------------------
#define BQ   64
#define BKV  64
#define QLD  (HD + 4)    // 132: padded row stride for Q/K/V tiles
#define PLD  (BKV + 1)   // 65:  padded row stride for P tile

#define ATTN_SMEM_FLOATS (3 * BQ * QLD + BQ * PLD)
#define ATTN_SMEM_BYTES  (ATTN_SMEM_FLOATS * 4)

__global__ __launch_bounds__(256, 1)
void attn_kernel(const float* __restrict__ qkv, float* __restrict__ out)
{
    extern __shared__ float sm[];
    float* Qs = sm;                    // BQ * QLD
    float* Ks = Qs + BQ * QLD;
    float* Vs = Ks + BQ * QLD;
    float* Ps = Vs + BQ * QLD;         // BQ * PLD

    const int tid = threadIdx.x;
    const int tx  = tid & 15;
    const int ty  = tid >> 4;
    const int qb  = blockIdx.x;        // q tile index
    const int bh  = blockIdx.y;
    const int h   = bh & (NH - 1);
    const int b   = bh >> 4;

    const float scale = rsqrtf((float)HD);

    // ---- load Q tile: 64 rows x 128 cols = 2048 float4 / 256 thr = 8 each
    #pragma unroll
    for (int i = 0; i < 8; i++) {
        int e  = tid + i * 256;
        int r  = e >> 5;               // 0..63
        int c4 = e & 31;               // 0..31
        int s  = qb * BQ + r;
        float4 v = *reinterpret_cast<const float4*>(
            &qkv[(size_t)(b * SEQ + s) * QKV_N + h * HD + c4 * 4]);
        *reinterpret_cast<float4*>(&Qs[r * QLD + c4 * 4]) = v;
    }

    float m_run[4], l_run[4], o_acc[4][8];
    #pragma unroll
    for (int i = 0; i < 4; i++) {
        m_run[i] = -1e30f; l_run[i] = 0.f;
        #pragma unroll
        for (int j = 0; j < 8; j++) o_acc[i][j] = 0.f;
    }

    const int ntiles = qb + 1;  // causal: only tiles up to the diagonal
    for (int kt = 0; kt < ntiles; kt++) {
        __syncthreads();  // Q visible (1st iter); prev-iter Ps/Vs reads done

        // ---- load K, V tiles
        #pragma unroll
        for (int i = 0; i < 8; i++) {
            int e  = tid + i * 256;
            int r  = e >> 5;
            int c4 = e & 31;
            int s  = kt * BKV + r;
            size_t base = (size_t)(b * SEQ + s) * QKV_N + h * HD + c4 * 4;
            float4 kv = *reinterpret_cast<const float4*>(&qkv[base + EMB]);
            float4 vv = *reinterpret_cast<const float4*>(&qkv[base + 2 * EMB]);
            *reinterpret_cast<float4*>(&Ks[r * QLD + c4 * 4]) = kv;
            *reinterpret_cast<float4*>(&Vs[r * QLD + c4 * 4]) = vv;
        }
        __syncthreads();

        // ---- scores S = Q K^T (microtile 4x4)
        float sc[4][4];
        #pragma unroll
        for (int i = 0; i < 4; i++)
            #pragma unroll
            for (int j = 0; j < 4; j++) sc[i][j] = 0.f;

        #pragma unroll
        for (int kd = 0; kd < HD; kd += 4) {
            float4 a[4], bb[4];
            #pragma unroll
            for (int i = 0; i < 4; i++)
                a[i] = *reinterpret_cast<const float4*>(&Qs[(ty*4 + i) * QLD + kd]);
            #pragma unroll
            for (int j = 0; j < 4; j++)
                bb[j] = *reinterpret_cast<const float4*>(&Ks[(tx + 16*j) * QLD + kd]);
            #pragma unroll
            for (int i = 0; i < 4; i++)
                #pragma unroll
                for (int j = 0; j < 4; j++)
                    sc[i][j] += a[i].x*bb[j].x + a[i].y*bb[j].y
                              + a[i].z*bb[j].z + a[i].w*bb[j].w;
        }

        // ---- mask + scale
        #pragma unroll
        for (int i = 0; i < 4; i++) {
            int qi = qb * BQ + ty * 4 + i;
            #pragma unroll
            for (int j = 0; j < 4; j++) {
                int ki = kt * BKV + tx + 16 * j;
                sc[i][j] = (ki <= qi) ? sc[i][j] * scale : -1e30f;
            }
        }

        // ---- online softmax (row groups = 16 consecutive lanes)
        float alpha[4];
        #pragma unroll
        for (int i = 0; i < 4; i++) {
            float mx = fmaxf(fmaxf(sc[i][0], sc[i][1]), fmaxf(sc[i][2], sc[i][3]));
            #pragma unroll
            for (int off = 8; off >= 1; off >>= 1)
                mx = fmaxf(mx, __shfl_xor_sync(0xffffffffu, mx, off));
            float m_new = fmaxf(m_run[i], mx);
            alpha[i] = __expf(m_run[i] - m_new);
            m_run[i] = m_new;

            float rsum = 0.f;
            #pragma unroll
            for (int j = 0; j < 4; j++) {
                float p = __expf(sc[i][j] - m_new);
                sc[i][j] = p;
                rsum += p;
            }
            #pragma unroll
            for (int off = 8; off >= 1; off >>= 1)
                rsum += __shfl_xor_sync(0xffffffffu, rsum, off);
            l_run[i] = l_run[i] * alpha[i] + rsum;
        }

        // ---- stage P to shared
        #pragma unroll
        for (int i = 0; i < 4; i++)
            #pragma unroll
            for (int j = 0; j < 4; j++)
                Ps[(ty*4 + i) * PLD + tx + 16*j] = sc[i][j];
        __syncthreads();

        // ---- O = alpha*O + P V
        #pragma unroll
        for (int i = 0; i < 4; i++)
            #pragma unroll
            for (int j = 0; j < 8; j++) o_acc[i][j] *= alpha[i];

        #pragma unroll 4
        for (int kk = 0; kk < BKV; kk++) {
            float p0 = Ps[(ty*4 + 0) * PLD + kk];
            float p1 = Ps[(ty*4 + 1) * PLD + kk];
            float p2 = Ps[(ty*4 + 2) * PLD + kk];
            float p3 = Ps[(ty*4 + 3) * PLD + kk];
            float4 v0 = *reinterpret_cast<const float4*>(&Vs[kk * QLD + tx*8]);
            float4 v1 = *reinterpret_cast<const float4*>(&Vs[kk * QLD + tx*8 + 4]);
            float vv[8] = {v0.x, v0.y, v0.z, v0.w, v1.x, v1.y, v1.z, v1.w};
            #pragma unroll
            for (int j = 0; j < 8; j++) {
                o_acc[0][j] += p0 * vv[j];
                o_acc[1][j] += p1 * vv[j];
                o_acc[2][j] += p2 * vv[j];
                o_acc[3][j] += p3 * vv[j];
            }
        }
    }

    // ---- normalize + store: out[b][s][h*HD + c]
    #pragma unroll
    for (int i = 0; i < 4; i++) {
        int s = qb * BQ + ty * 4 + i;
        float inv = 1.f / l_run[i];
        size_t base = (size_t)(b * SEQ + s) * EMB + h * HD + tx * 8;
        float4 w0 = make_float4(o_acc[i][0]*inv, o_acc[i][1]*inv,
                                o_acc[i][2]*inv, o_acc[i][3]*inv);
        float4 w1 = make_float4(o_acc[i][4]*inv, o_acc[i][5]*inv,
                                o_acc[i][6]*inv, o_acc[i][7]*inv);
        *reinterpret_cast<float4*>(&out[base])     = w0;
        *reinterpret_cast<float4*>(&out[base + 4]) = w1;
    }
}

// ---------------------------------------------------------------------------
// Launch
// ---------------------------------------------------------------------------
extern "C" void kernel_launch(void* const* d_in, const int* in_sizes, int n_in,
                              void* d_out, int out_size)
{
    const float* x    = (const float*)d_in[0];
    const float* Wqkv = (const float*)d_in[1];
    const float* Wo   = (const float*)d_in[2];
    const float* fc   = (const float*)d_in[3];
    float* out        = (float*)d_out;

    float *qkv, *att;
    cudaGetSymbolAddress((void**)&qkv, g_qkv);
    cudaGetSymbolAddress((void**)&att, g_att);

    cudaFuncSetAttribute(attn_kernel,
                         cudaFuncAttributeMaxDynamicSharedMemorySize,
                         ATTN_SMEM_BYTES);

    // 1) qkv = x @ Wqkv : [4096,2048] x [2048,6144]
    {
        dim3 grid(QKV_N / 128, MROWS / 128);
        sgemm_kernel<128,128,16,8,8><<<grid, 256>>>(x, Wqkv, qkv, MROWS, QKV_N, EMB);
    }

    // 2) RoPE on q,k in place
    {
        int total  = BATCH * SEQ * 2 * NH * (HD / 2);
        int blocks = (total + 255) / 256;
        rope_kernel<<<blocks, 256>>>(qkv, fc);
    }

    // 3) causal flash attention
    {
        dim3 grid(SEQ / BQ, BATCH * NH);
        attn_kernel<<<grid, 256, ATTN_SMEM_BYTES>>>(qkv, att);
    }

    // 4) out = att @ Wo : [4096,2048] x [2048,2048]
    {
        dim3 grid(EMB / 128, MROWS / 128);
        sgemm_kernel<128,128,16,8,8><<<grid, 256>>>(att, Wo, out, MROWS, EMB, EMB);
    }
}

// round 4
// speedup vs baseline: 1.8333x; 1.8333x over previous
#include <cuda_runtime.h>
#include <math.h>
#include <stdint.h>

// Problem constants
#define BATCH 2
#define SEQ   2048
#define EMB   2048
#define NH    16
#define HD    128          // head dim
#define QKV_N (3*EMB)      // 6144
#define MROWS (BATCH*SEQ)  // 4096

// ---------------------------------------------------------------------------
// Scratch (static __device__ arrays: allocation-free per harness rules)
// ---------------------------------------------------------------------------
__device__ float g_qkv[(size_t)BATCH*SEQ*QKV_N];   // 100.7 MB  (qkv activations)
__device__ float g_att[(size_t)BATCH*SEQ*EMB];     // 33.6 MB   (attn out, tf32-rounded)
__device__ float g_xt[(size_t)BATCH*SEQ*EMB];      // 33.6 MB   (x, tf32-rounded)
__device__ float g_wqkvt[(size_t)EMB*QKV_N];       // 50.3 MB   (Wqkv, tf32-rounded)
__device__ float g_wot[(size_t)EMB*EMB];           // 16.8 MB   (Wo, tf32-rounded)

// ---------------------------------------------------------------------------
// tf32 helpers
// ---------------------------------------------------------------------------
__device__ __forceinline__ float f2tf32(float x) {
    uint32_t r;
    asm("cvt.rna.tf32.f32 %0, %1;" : "=r"(r) : "f"(x));
    return __uint_as_float(r);
}

__global__ void cvt_tf32_kernel(const float* __restrict__ in,
                                float* __restrict__ out, int n4)
{
    int i = blockIdx.x * blockDim.x + threadIdx.x;
    if (i >= n4) return;
    float4 v = reinterpret_cast<const float4*>(in)[i];
    v.x = f2tf32(v.x); v.y = f2tf32(v.y); v.z = f2tf32(v.z); v.w = f2tf32(v.w);
    reinterpret_cast<float4*>(out)[i] = v;
}

__device__ __forceinline__ void mma_tf32(float d[4], const uint32_t a[4],
                                         const uint32_t b[2])
{
    asm volatile(
        "mma.sync.aligned.m16n8k8.row.col.f32.tf32.tf32.f32 "
        "{%0,%1,%2,%3}, {%4,%5,%6,%7}, {%8,%9}, {%0,%1,%2,%3};\n"
        : "+f"(d[0]), "+f"(d[1]), "+f"(d[2]), "+f"(d[3])
        : "r"(a[0]), "r"(a[1]), "r"(a[2]), "r"(a[3]),
          "r"(b[0]), "r"(b[1]));
}

// ---------------------------------------------------------------------------
// tf32 tensor-core GEMM: C[M,N] = A[M,K] * B[K,N], row-major fp32 storage,
// operands pre-rounded to tf32. 128x128x32 block tile, 256 threads,
// 8 warps in 4x2 grid, warp tile 32x64 (2x8 m16n8k8 frags).
// cp.async double-buffered stages.
// A smem: [128][36]  (pad 4 -> fragment loads conflict-free: bank=(4g+q)%32)
// B smem: [32][136]  (pad 8 -> fragment loads conflict-free: bank=(8q+g)%32)
// ---------------------------------------------------------------------------
#define G_ALD 36
#define G_BLD 136
#define G_ASZ (128 * G_ALD)   // floats
#define G_BSZ (32 * G_BLD)
#define GEMM_SMEM_BYTES (2 * (G_ASZ + G_BSZ) * 4)   // 71680

__global__ __launch_bounds__(256, 1)
void gemm_tf32_kernel(const float* __restrict__ A, const float* __restrict__ B,
                      float* __restrict__ C, int M, int N, int K)
{
    extern __shared__ float smg[];
    float* As0 = smg;
    float* Bs0 = smg + G_ASZ;
    float* As1 = smg + G_ASZ + G_BSZ;
    float* Bs1 = smg + 2 * G_ASZ + G_BSZ;

    const int tid  = threadIdx.x;
    const int lane = tid & 31;
    const int warp = tid >> 5;
    const int wm   = warp >> 1;     // 0..3
    const int wn   = warp & 1;      // 0..1
    const int grp  = lane >> 2;     // 0..7
    const int qid  = lane & 3;      // 0..3
    const int rowBase = blockIdx.y * 128;
    const int colBase = blockIdx.x * 128;

    float acc[2][8][4];
    #pragma unroll
    for (int mi = 0; mi < 2; mi++)
        #pragma unroll
        for (int ni = 0; ni < 8; ni++)
            #pragma unroll
            for (int t = 0; t < 4; t++) acc[mi][ni][t] = 0.f;

    auto loadStage = [&](float* As, float* Bs, int k0) {
        // A tile: 128 rows x 32 cols = 1024 16B chunks (4/thread)
        #pragma unroll
        for (int i = 0; i < 4; i++) {
            int e  = tid + i * 256;
            int r  = e >> 3;          // 0..127
            int c4 = e & 7;           // 0..7
            const float* g = &A[(size_t)(rowBase + r) * K + k0 + c4 * 4];
            uint32_t s = (uint32_t)__cvta_generic_to_shared(&As[r * G_ALD + c4 * 4]);
            asm volatile("cp.async.cg.shared.global [%0], [%1], 16;\n"
                         :: "r"(s), "l"(g));
        }
        // B tile: 32 rows x 128 cols = 1024 16B chunks (4/thread)
        #pragma unroll
        for (int i = 0; i < 4; i++) {
            int e  = tid + i * 256;
            int r  = e >> 5;          // 0..31
            int c4 = e & 31;          // 0..31
            const float* g = &B[(size_t)(k0 + r) * N + colBase + c4 * 4];
            uint32_t s = (uint32_t)__cvta_generic_to_shared(&Bs[r * G_BLD + c4 * 4]);
            asm volatile("cp.async.cg.shared.global [%0], [%1], 16;\n"
                         :: "r"(s), "l"(g));
        }
        asm volatile("cp.async.commit_group;\n");
    };

    const int nstages = K / 32;
    loadStage(As0, Bs0, 0);

    for (int s = 0; s < nstages; s++) {
        asm volatile("cp.async.wait_group 0;\n");
        __syncthreads();
        if (s + 1 < nstages) {
            if ((s + 1) & 1) loadStage(As1, Bs1, (s + 1) * 32);
            else             loadStage(As0, Bs0, (s + 1) * 32);
        }
        const float* a_s = (s & 1) ? As1 : As0;
        const float* b_s = (s & 1) ? Bs1 : Bs0;

        #pragma unroll
        for (int ks = 0; ks < 4; ks++) {
            const int k0 = ks * 8;
            uint32_t af[2][4], bf[8][2];
            #pragma unroll
            for (int mi = 0; mi < 2; mi++) {
                int r0 = wm * 32 + mi * 16 + grp;
                af[mi][0] = __float_as_uint(a_s[(r0    ) * G_ALD + k0 + qid]);
                af[mi][1] = __float_as_uint(a_s[(r0 + 8) * G_ALD + k0 + qid]);
                af[mi][2] = __float_as_uint(a_s[(r0    ) * G_ALD + k0 + qid + 4]);
                af[mi][3] = __float_as_uint(a_s[(r0 + 8) * G_ALD + k0 + qid + 4]);
            }
            #pragma unroll
            for (int ni = 0; ni < 8; ni++) {
                int c = wn * 64 + ni * 8 + grp;
                bf[ni][0] = __float_as_uint(b_s[(k0 + qid    ) * G_BLD + c]);
                bf[ni][1] = __float_as_uint(b_s[(k0 + qid + 4) * G_BLD + c]);
            }
            #pragma unroll
            for (int mi = 0; mi < 2; mi++)
                #pragma unroll
                for (int ni = 0; ni < 8; ni++)
                    mma_tf32(acc[mi][ni], af[mi], bf[ni]);
        }
        // no trailing sync needed: next iteration's wait+sync protects buffers
    }

    // Epilogue
    #pragma unroll
    for (int mi = 0; mi < 2; mi++) {
        int r = rowBase + wm * 32 + mi * 16 + grp;
        #pragma unroll
        for (int ni = 0; ni < 8; ni++) {
            int c = colBase + wn * 64 + ni * 8 + qid * 2;
            float2 v0 = make_float2(acc[mi][ni][0], acc[mi][ni][1]);
            float2 v1 = make_float2(acc[mi][ni][2], acc[mi][ni][3]);
            *reinterpret_cast<float2*>(&C[(size_t)r * N + c])       = v0;
            *reinterpret_cast<float2*>(&C[(size_t)(r + 8) * N + c]) = v1;
        }
    }
}

// ---------------------------------------------------------------------------
// RoPE: rotate interleaved pairs within each head of q and k, in place.
// freqs_cis layout: [S][D/2][2] = (cos, sin)
// ---------------------------------------------------------------------------
__global__ void rope_kernel(float* __restrict__ qkv, const float* __restrict__ fc)
{
    int idx = blockIdx.x * blockDim.x + threadIdx.x;
    const int total = BATCH * SEQ * 2 * NH * (HD / 2);
    if (idx >= total) return;

    int p  = idx & (HD/2 - 1);       // 0..63
    int t  = idx >> 6;
    int h2 = t & (2*NH - 1);         // 0..31: [0,NH) = q heads, [NH,2NH) = k heads
    t >>= 5;
    int s  = t & (SEQ - 1);
    int b  = t >> 11;

    float c  = fc[(s * (HD/2) + p) * 2 + 0];
    float sn = fc[(s * (HD/2) + p) * 2 + 1];

    size_t off = (size_t)(b * SEQ + s) * QKV_N + 2 * p;
    off += (h2 < NH) ? (size_t)h2 * HD : (size_t)EMB + (size_t)(h2 - NH) * HD;

    float x0 = qkv[off], x1 = qkv[off + 1];
    qkv[off]     = x0 * c - x1 * sn;
    qkv[off + 1] = x1 * c + x0 * sn;
}

// ---------------------------------------------------------------------------
// Flash-style causal attention (fp32 scalar this round). One block per
// (q-tile of 64, b*h). Output is tf32-rounded at store so the projection
// GEMM can consume it directly.
// ---------------------------------------------------------------------------
#define BQ   64
#define BKV  64
#define QLD  (HD + 4)    // 132
#define PLD  (BKV + 1)   // 65

#define ATTN_SMEM_FLOATS (3 * BQ * QLD + BQ * PLD)
#define ATTN_SMEM_BYTES  (ATTN_SMEM_FLOATS * 4)

__global__ __launch_bounds__(256, 1)
void attn_kernel(const float* __restrict__ qkv, float* __restrict__ out)
{
    extern __shared__ float sm[];
    float* Qs = sm;
    float* Ks = Qs + BQ * QLD;
    float* Vs = Ks + BQ * QLD;
    float* Ps = Vs + BQ * QLD;

    const int tid = threadIdx.x;
    const int tx  = tid & 15;
    const int ty  = tid >> 4;
    const int qb  = blockIdx.x;
    const int bh  = blockIdx.y;
    const int h   = bh & (NH - 1);
    const int b   = bh >> 4;

    const float scale = rsqrtf((float)HD);

    #pragma unroll
    for (int i = 0; i < 8; i++) {
        int e  = tid + i * 256;
        int r  = e >> 5;
        int c4 = e & 31;
        int s  = qb * BQ + r;
        float4 v = *reinterpret_cast<const float4*>(
            &qkv[(size_t)(b * SEQ + s) * QKV_N + h * HD + c4 * 4]);
        *reinterpret_cast<float4*>(&Qs[r * QLD + c4 * 4]) = v;
    }

    float m_run[4], l_run[4], o_acc[4][8];
    #pragma unroll
    for (int i = 0; i < 4; i++) {
        m_run[i] = -1e30f; l_run[i] = 0.f;
        #pragma unroll
        for (int j = 0; j < 8; j++) o_acc[i][j] = 0.f;
    }

    const int ntiles = qb + 1;
    for (int kt = 0; kt < ntiles; kt++) {
        __syncthreads();

        #pragma unroll
        for (int i = 0; i < 8; i++) {
            int e  = tid + i * 256;
            int r  = e >> 5;
            int c4 = e & 31;
            int s  = kt * BKV + r;
            size_t base = (size_t)(b * SEQ + s) * QKV_N + h * HD + c4 * 4;
            float4 kv = *reinterpret_cast<const float4*>(&qkv[base + EMB]);
            float4 vv = *reinterpret_cast<const float4*>(&qkv[base + 2 * EMB]);
            *reinterpret_cast<float4*>(&Ks[r * QLD + c4 * 4]) = kv;
            *reinterpret_cast<float4*>(&Vs[r * QLD + c4 * 4]) = vv;
        }
        __syncthreads();

        float sc[4][4];
        #pragma unroll
        for (int i = 0; i < 4; i++)
            #pragma unroll
            for (int j = 0; j < 4; j++) sc[i][j] = 0.f;

        #pragma unroll
        for (int kd = 0; kd < HD; kd += 4) {
            float4 a[4], bb[4];
            #pragma unroll
            for (int i = 0; i < 4; i++)
                a[i] = *reinterpret_cast<const float4*>(&Qs[(ty*4 + i) * QLD + kd]);
            #pragma unroll
            for (int j = 0; j < 4; j++)
                bb[j] = *reinterpret_cast<const float4*>(&Ks[(tx + 16*j) * QLD + kd]);
            #pragma unroll
            for (int i = 0; i < 4; i++)
                #pragma unroll
                for (int j = 0; j < 4; j++)
                    sc[i][j] += a[i].x*bb[j].x + a[i].y*bb[j].y
                              + a[i].z*bb[j].z + a[i].w*bb[j].w;
        }

        #pragma unroll
        for (int i = 0; i < 4; i++) {
            int qi = qb * BQ + ty * 4 + i;
            #pragma unroll
            for (int j = 0; j < 4; j++) {
                int ki = kt * BKV + tx + 16 * j;
                sc[i][j] = (ki <= qi) ? sc[i][j] * scale : -1e30f;
            }
        }

        float alpha[4];
        #pragma unroll
        for (int i = 0; i < 4; i++) {
            float mx = fmaxf(fmaxf(sc[i][0], sc[i][1]), fmaxf(sc[i][2], sc[i][3]));
            #pragma unroll
            for (int off = 8; off >= 1; off >>= 1)
                mx = fmaxf(mx, __shfl_xor_sync(0xffffffffu, mx, off));
            float m_new = fmaxf(m_run[i], mx);
            alpha[i] = __expf(m_run[i] - m_new);
            m_run[i] = m_new;

            float rsum = 0.f;
            #pragma unroll
            for (int j = 0; j < 4; j++) {
                float p = __expf(sc[i][j] - m_new);
                sc[i][j] = p;
                rsum += p;
            }
            #pragma unroll
            for (int off = 8; off >= 1; off >>= 1)
                rsum += __shfl_xor_sync(0xffffffffu, rsum, off);
            l_run[i] = l_run[i] * alpha[i] + rsum;
        }

        #pragma unroll
        for (int i = 0; i < 4; i++)
            #pragma unroll
            for (int j = 0; j < 4; j++)
                Ps[(ty*4 + i) * PLD + tx + 16*j] = sc[i][j];
        __syncthreads();

        #pragma unroll
        for (int i = 0; i < 4; i++)
            #pragma unroll
            for (int j = 0; j < 8; j++) o_acc[i][j] *= alpha[i];

        #pragma unroll 4
        for (int kk = 0; kk < BKV; kk++) {
            float p0 = Ps[(ty*4 + 0) * PLD + kk];
            float p1 = Ps[(ty*4 + 1) * PLD + kk];
            float p2 = Ps[(ty*4 + 2) * PLD + kk];
            float p3 = Ps[(ty*4 + 3) * PLD + kk];
            float4 v0 = *reinterpret_cast<const float4*>(&Vs[kk * QLD + tx*8]);
            float4 v1 = *reinterpret_cast<const float4*>(&Vs[kk * QLD + tx*8 + 4]);
            float vv[8] = {v0.x, v0.y, v0.z, v0.w, v1.x, v1.y, v1.z, v1.w};
            #pragma unroll
            for (int j = 0; j < 8; j++) {
                o_acc[0][j] += p0 * vv[j];
                o_acc[1][j] += p1 * vv[j];
                o_acc[2][j] += p2 * vv[j];
                o_acc[3][j] += p3 * vv[j];
            }
        }
    }

    // normalize + tf32-round + store
    #pragma unroll
    for (int i = 0; i < 4; i++) {
        int s = qb * BQ + ty * 4 + i;
        float inv = 1.f / l_run[i];
        size_t base = (size_t)(b * SEQ + s) * EMB + h * HD + tx * 8;
        float4 w0 = make_float4(f2tf32(o_acc[i][0]*inv), f2tf32(o_acc[i][1]*inv),
                                f2tf32(o_acc[i][2]*inv), f2tf32(o_acc[i][3]*inv));
        float4 w1 = make_float4(f2tf32(o_acc[i][4]*inv), f2tf32(o_acc[i][5]*inv),
                                f2tf32(o_acc[i][6]*inv), f2tf32(o_acc[i][7]*inv));
        *reinterpret_cast<float4*>(&out[base])     = w0;
        *reinterpret_cast<float4*>(&out[base + 4]) = w1;
    }
}

// ---------------------------------------------------------------------------
// Launch
// ---------------------------------------------------------------------------
extern "C" void kernel_launch(void* const* d_in, const int* in_sizes, int n_in,
                              void* d_out, int out_size)
{
    const float* x    = (const float*)d_in[0];
    const float* Wqkv = (const float*)d_in[1];
    const float* Wo   = (const float*)d_in[2];
    const float* fc   = (const float*)d_in[3];
    float* out        = (float*)d_out;

    float *qkv, *att, *xt, *wqkvt, *wot;
    cudaGetSymbolAddress((void**)&qkv,   g_qkv);
    cudaGetSymbolAddress((void**)&att,   g_att);
    cudaGetSymbolAddress((void**)&xt,    g_xt);
    cudaGetSymbolAddress((void**)&wqkvt, g_wqkvt);
    cudaGetSymbolAddress((void**)&wot,   g_wot);

    cudaFuncSetAttribute(attn_kernel,
                         cudaFuncAttributeMaxDynamicSharedMemorySize,
                         ATTN_SMEM_BYTES);
    cudaFuncSetAttribute(gemm_tf32_kernel,
                         cudaFuncAttributeMaxDynamicSharedMemorySize,
                         GEMM_SMEM_BYTES);

    // 0) pre-round GEMM operands to tf32
    {
        int n4;
        n4 = (MROWS * EMB) / 4;
        cvt_tf32_kernel<<<(n4 + 255) / 256, 256>>>(x, xt, n4);
        n4 = (EMB * QKV_N) / 4;
        cvt_tf32_kernel<<<(n4 + 255) / 256, 256>>>(Wqkv, wqkvt, n4);
        n4 = (EMB * EMB) / 4;
        cvt_tf32_kernel<<<(n4 + 255) / 256, 256>>>(Wo, wot, n4);
    }

    // 1) qkv = x @ Wqkv : [4096,2048] x [2048,6144]  (tf32 tensor cores)
    {
        dim3 grid(QKV_N / 128, MROWS / 128);
        gemm_tf32_kernel<<<grid, 256, GEMM_SMEM_BYTES>>>(xt, wqkvt, qkv,
                                                         MROWS, QKV_N, EMB);
    }

    // 2) RoPE on q,k in place
    {
        int total  = BATCH * SEQ * 2 * NH * (HD / 2);
        int blocks = (total + 255) / 256;
        rope_kernel<<<blocks, 256>>>(qkv, fc);
    }

    // 3) causal flash attention (writes tf32-rounded activations)
    {
        dim3 grid(SEQ / BQ, BATCH * NH);
        attn_kernel<<<grid, 256, ATTN_SMEM_BYTES>>>(qkv, att);
    }

    // 4) out = att @ Wo : [4096,2048] x [2048,2048]  (tf32 tensor cores)
    {
        dim3 grid(EMB / 128, MROWS / 128);
        gemm_tf32_kernel<<<grid, 256, GEMM_SMEM_BYTES>>>(att, wot, out,
                                                         MROWS, EMB, EMB);
    }
}

// round 5
// speedup vs baseline: 1.9238x; 1.0494x over previous
#include <cuda_runtime.h>
#include <math.h>
#include <stdint.h>

// Problem constants
#define BATCH 2
#define SEQ   2048
#define EMB   2048
#define NH    16
#define HD    128
#define QKV_N (3*EMB)      // 6144
#define MROWS (BATCH*SEQ)  // 4096

// ---------------------------------------------------------------------------
// Scratch
// ---------------------------------------------------------------------------
__device__ float g_qkv[(size_t)MROWS*QKV_N];    // qkv activations (fp32)
__device__ float g_att[(size_t)MROWS*EMB];      // attn out (tf32-rounded)
__device__ float g_xt[(size_t)MROWS*EMB];       // x tf32-rounded
__device__ float g_wqkvt[(size_t)EMB*QKV_N];    // Wqkv^T  [6144][2048] tf32
__device__ float g_wot[(size_t)EMB*EMB];        // Wo^T    [2048][2048] tf32

// ---------------------------------------------------------------------------
// helpers
// ---------------------------------------------------------------------------
__device__ __forceinline__ float f2tf32(float x) {
    uint32_t r;
    asm("cvt.rna.tf32.f32 %0, %1;" : "=r"(r) : "f"(x));
    return __uint_as_float(r);
}

__device__ __forceinline__ void mma_tf32(float d[4], const uint32_t a[4],
                                         uint32_t b0, uint32_t b1)
{
    asm volatile(
        "mma.sync.aligned.m16n8k8.row.col.f32.tf32.tf32.f32 "
        "{%0,%1,%2,%3}, {%4,%5,%6,%7}, {%8,%9}, {%0,%1,%2,%3};\n"
        : "+f"(d[0]), "+f"(d[1]), "+f"(d[2]), "+f"(d[3])
        : "r"(a[0]), "r"(a[1]), "r"(a[2]), "r"(a[3]), "r"(b0), "r"(b1));
}

__device__ __forceinline__ void ldsm4(uint32_t r[4], uint32_t addr) {
    asm volatile("ldmatrix.sync.aligned.m8n8.x4.shared.b16 {%0,%1,%2,%3}, [%4];"
        : "=r"(r[0]), "=r"(r[1]), "=r"(r[2]), "=r"(r[3]) : "r"(addr));
}

#define CP16(dst_u32, src_ptr) \
    asm volatile("cp.async.cg.shared.global [%0], [%1], 16;" \
                 :: "r"(dst_u32), "l"(src_ptr))

// ---------------------------------------------------------------------------
// tf32 round (elementwise) and tf32 round + transpose
// ---------------------------------------------------------------------------
__global__ void cvt_tf32_kernel(const float* __restrict__ in,
                                float* __restrict__ out, int n4)
{
    int i = blockIdx.x * blockDim.x + threadIdx.x;
    if (i >= n4) return;
    float4 v = reinterpret_cast<const float4*>(in)[i];
    v.x = f2tf32(v.x); v.y = f2tf32(v.y); v.z = f2tf32(v.z); v.w = f2tf32(v.w);
    reinterpret_cast<float4*>(out)[i] = v;
}

// in: [R][C] -> out: [C][R], tf32-rounded. R, C multiples of 32.
__global__ void transpose_tf32_kernel(const float* __restrict__ in,
                                      float* __restrict__ out, int R, int C)
{
    __shared__ float t[32][33];
    int bx = blockIdx.x * 32;   // col tile
    int by = blockIdx.y * 32;   // row tile
    int x = bx + threadIdx.x;
    #pragma unroll
    for (int i = threadIdx.y; i < 32; i += 8)
        t[i][threadIdx.x] = f2tf32(in[(size_t)(by + i) * C + x]);
    __syncthreads();
    int xo = by + threadIdx.x;
    #pragma unroll
    for (int i = threadIdx.y; i < 32; i += 8)
        out[(size_t)(bx + i) * R + xo] = t[threadIdx.x][i];
}

// ---------------------------------------------------------------------------
// tf32 GEMM v2 (ldmatrix-fed): C[M,N] = A[M,K] * Bt[N,K]^T
// 128x128x32 tile, 256 thr, 8 warps 4x2, warp tile 32x64. 4-stage cp.async.
// smem per stage: As[128][36] + Bs[128][36]
// ---------------------------------------------------------------------------
#define GLD 36
#define STG_FLOATS (2 * 128 * GLD)               // 9216 floats / stage
#define GSTAGES 4
#define GEMM_SMEM_BYTES (GSTAGES * STG_FLOATS * 4)  // 147456

__global__ __launch_bounds__(256, 1)
void gemm_tf32_v2(const float* __restrict__ A, const float* __restrict__ Bt,
                  float* __restrict__ C, int M, int N, int K)
{
    extern __shared__ float smg[];
    const int tid  = threadIdx.x;
    const int lane = tid & 31;
    const int warp = tid >> 5;
    const int wm   = warp >> 1;    // 0..3
    const int wn   = warp & 1;     // 0..1
    const int g    = lane >> 2;    // groupID
    const int tig  = lane & 3;

    // panel raster: iterate 8 column-blocks x all row-blocks per panel (L2 reuse)
    const int PANEL = 8;
    int bid = blockIdx.x + blockIdx.y * gridDim.x;
    int per_panel = PANEL * gridDim.y;
    int p  = bid / per_panel;
    int rr = bid % per_panel;
    int by = rr / PANEL;
    int bx = p * PANEL + (rr % PANEL);
    const int rowBase = by * 128;
    const int colBase = bx * 128;

    const uint32_t smemU = (uint32_t)__cvta_generic_to_shared(smg);

    // ldmatrix lane roles
    const int selL = lane >> 3, rL = lane & 7;
    const int aRow = (selL & 1) * 8 + rL, aCol = (selL >> 1) * 4;
    const int bRow = rL,                  bCol = selL * 4;

    float acc[2][8][4];
    #pragma unroll
    for (int mi = 0; mi < 2; mi++)
        #pragma unroll
        for (int ni = 0; ni < 8; ni++)
            #pragma unroll
            for (int t = 0; t < 4; t++) acc[mi][ni][t] = 0.f;

    auto loadStage = [&](int st, int k0) {
        uint32_t stBase = smemU + st * STG_FLOATS * 4;
        #pragma unroll
        for (int i = 0; i < 4; i++) {
            int e = tid + i * 256;          // 0..1023
            int r = e >> 3, c = e & 7;      // 128 rows x 8 chunks
            CP16(stBase + (r * GLD + c * 4) * 4,
                 &A[(size_t)(rowBase + r) * K + k0 + c * 4]);
        }
        #pragma unroll
        for (int i = 0; i < 4; i++) {
            int e = tid + i * 256;
            int r = e >> 3, c = e & 7;
            CP16(stBase + (128 * GLD + r * GLD + c * 4) * 4,
                 &Bt[(size_t)(colBase + r) * K + k0 + c * 4]);
        }
        asm volatile("cp.async.commit_group;");
    };

    const int nst = K / 32;
    loadStage(0, 0);
    loadStage(1, 32);
    loadStage(2, 64);

    for (int s = 0; s < nst; s++) {
        asm volatile("cp.async.wait_group 2;");
        __syncthreads();
        if (s + 3 < nst) loadStage((s + 3) & 3, (s + 3) * 32);

        const int st = s & 3;
        uint32_t aBase = smemU + (st * STG_FLOATS
                         + (wm * 32 + aRow) * GLD + aCol) * 4;
        uint32_t bBase = smemU + (st * STG_FLOATS + 128 * GLD
                         + (wn * 64 + bRow) * GLD + bCol) * 4;

        #pragma unroll
        for (int kk = 0; kk < 2; kk++) {
            const int k0 = kk * 16;
            uint32_t bf[8][4];
            #pragma unroll
            for (int ni = 0; ni < 8; ni++)
                ldsm4(bf[ni], bBase + (ni * 8 * GLD + k0) * 4);
            uint32_t af[2][2][4];
            #pragma unroll
            for (int mi = 0; mi < 2; mi++) {
                ldsm4(af[mi][0], aBase + (mi * 16 * GLD + k0) * 4);
                ldsm4(af[mi][1], aBase + (mi * 16 * GLD + k0 + 8) * 4);
            }
            #pragma unroll
            for (int hh = 0; hh < 2; hh++)
                #pragma unroll
                for (int mi = 0; mi < 2; mi++)
                    #pragma unroll
                    for (int ni = 0; ni < 8; ni++)
                        mma_tf32(acc[mi][ni], af[mi][hh],
                                 bf[ni][2*hh], bf[ni][2*hh + 1]);
        }
    }

    #pragma unroll
    for (int mi = 0; mi < 2; mi++) {
        int r0 = rowBase + wm * 32 + mi * 16 + g;
        #pragma unroll
        for (int ni = 0; ni < 8; ni++) {
            int c = colBase + wn * 64 + ni * 8 + tig * 2;
            *reinterpret_cast<float2*>(&C[(size_t)r0 * N + c]) =
                make_float2(acc[mi][ni][0], acc[mi][ni][1]);
            *reinterpret_cast<float2*>(&C[(size_t)(r0 + 8) * N + c]) =
                make_float2(acc[mi][ni][2], acc[mi][ni][3]);
        }
    }
}

// ---------------------------------------------------------------------------
// RoPE (unchanged)
// ---------------------------------------------------------------------------
__global__ void rope_kernel(float* __restrict__ qkv, const float* __restrict__ fc)
{
    int idx = blockIdx.x * blockDim.x + threadIdx.x;
    const int total = BATCH * SEQ * 2 * NH * (HD / 2);
    if (idx >= total) return;

    int p  = idx & (HD/2 - 1);
    int t  = idx >> 6;
    int h2 = t & (2*NH - 1);
    t >>= 5;
    int s  = t & (SEQ - 1);
    int b  = t >> 11;

    float c  = fc[(s * (HD/2) + p) * 2 + 0];
    float sn = fc[(s * (HD/2) + p) * 2 + 1];

    size_t off = (size_t)(b * SEQ + s) * QKV_N + 2 * p;
    off += (h2 < NH) ? (size_t)h2 * HD : (size_t)EMB + (size_t)(h2 - NH) * HD;

    float x0 = qkv[off], x1 = qkv[off + 1];
    qkv[off]     = x0 * c - x1 * sn;
    qkv[off + 1] = x1 * c + x0 * sn;
}

// ---------------------------------------------------------------------------
// Tensor-core causal flash attention.
// BQ=128, BKV=64. 8 warps; warp w owns q-rows [w*16, w*16+16) -> softmax
// fully warp-local. P staged via warp-private smem rows.
// ---------------------------------------------------------------------------
#define AQLD 132
#define AKLD 132
#define AVLD 68
#define APLD 68
#define ATT_K (128 * AQLD)
#define ATT_V (ATT_K + 64 * AKLD)
#define ATT_P (ATT_V + 128 * AVLD)
#define ATT_SMEM_FLOATS (ATT_P + 128 * APLD)
#define ATT_SMEM_BYTES  (ATT_SMEM_FLOATS * 4)   // 171008

__global__ __launch_bounds__(256, 1)
void attn_tc_kernel(const float* __restrict__ qkv, float* __restrict__ out)
{
    extern __shared__ float sm[];
    float* Qs = sm;
    float* Ks = sm + ATT_K;
    float* Vt = sm + ATT_V;
    float* Ps = sm + ATT_P;

    const int tid  = threadIdx.x;
    const int lane = tid & 31;
    const int warp = tid >> 5;
    const int g    = lane >> 2;
    const int tig  = lane & 3;
    const int w16  = warp * 16;

    const int qb = (gridDim.x - 1) - blockIdx.x;   // long CTAs first
    const int bh = blockIdx.y;
    const int h  = bh & (NH - 1);
    const int b  = bh >> 4;

    const float scale = 0.08838834764831845f;  // 1/sqrt(128)

    // ---- load Q (scaled + tf32): 128 rows x 32 16B-chunks
    #pragma unroll
    for (int i = 0; i < 16; i++) {
        int e = tid + i * 256;
        int r = e >> 5, c = e & 31;
        float4 v = *reinterpret_cast<const float4*>(
            &qkv[(size_t)(b * SEQ + qb * 128 + r) * QKV_N + h * HD + c * 4]);
        float4 o;
        o.x = f2tf32(v.x * scale); o.y = f2tf32(v.y * scale);
        o.z = f2tf32(v.z * scale); o.w = f2tf32(v.w * scale);
        *reinterpret_cast<float4*>(&Qs[r * AQLD + c * 4]) = o;
    }

    float m_run[2] = {-1e30f, -1e30f}, l_run[2] = {0.f, 0.f};
    float oacc[16][4];
    #pragma unroll
    for (int ni = 0; ni < 16; ni++)
        #pragma unroll
        for (int t = 0; t < 4; t++) oacc[ni][t] = 0.f;

    // ldmatrix lane roles
    const int selL = lane >> 3, rL = lane & 7;
    const int aRow = (selL & 1) * 8 + rL, aCol = (selL >> 1) * 4;
    const int bRow = rL,                  bCol = selL * 4;

    const uint32_t smemU = (uint32_t)__cvta_generic_to_shared(sm);
    const uint32_t qAddr  = smemU + ((w16 + aRow) * AQLD + aCol) * 4;
    const uint32_t kAddr  = smemU + (ATT_K + bRow * AKLD + bCol) * 4;
    const uint32_t pAddrA = smemU + (ATT_P + (w16 + aRow) * APLD + aCol) * 4;
    const uint32_t vAddr  = smemU + (ATT_V + bRow * AVLD + bCol) * 4;

    const int ntiles = 2 * qb + 2;
    for (int kt = 0; kt < ntiles; kt++) {
        __syncthreads();

        // ---- K tile (coalesced, tf32)
        #pragma unroll
        for (int i = 0; i < 8; i++) {
            int e = tid + i * 256;
            int r = e >> 5, c = e & 31;
            float4 v = *reinterpret_cast<const float4*>(
                &qkv[(size_t)(b * SEQ + kt * 64 + r) * QKV_N + EMB + h * HD + c * 4]);
            float4 o;
            o.x = f2tf32(v.x); o.y = f2tf32(v.y);
            o.z = f2tf32(v.z); o.w = f2tf32(v.w);
            *reinterpret_cast<float4*>(&Ks[r * AKLD + c * 4]) = o;
        }
        // ---- V tile transposed into Vt[d][kv] (tf32)
        #pragma unroll
        for (int i = 0; i < 8; i++) {
            int e  = tid + i * 256;
            int kv = e & 63, c4 = e >> 6;
            float4 v = *reinterpret_cast<const float4*>(
                &qkv[(size_t)(b * SEQ + kt * 64 + kv) * QKV_N + 2 * EMB + h * HD + c4 * 4]);
            int d0 = c4 * 4;
            Vt[(d0 + 0) * AVLD + kv] = f2tf32(v.x);
            Vt[(d0 + 1) * AVLD + kv] = f2tf32(v.y);
            Vt[(d0 + 2) * AVLD + kv] = f2tf32(v.z);
            Vt[(d0 + 3) * AVLD + kv] = f2tf32(v.w);
        }
        __syncthreads();

        // warp-level skip of fully-masked tiles
        if (kt * 64 > qb * 128 + w16 + 15) continue;

        // ---- S = Q K^T  (warp: 16 rows x 64 cols)
        float sc[8][4];
        #pragma unroll
        for (int ni = 0; ni < 8; ni++)
            #pragma unroll
            for (int t = 0; t < 4; t++) sc[ni][t] = 0.f;

        #pragma unroll
        for (int ks8 = 0; ks8 < 8; ks8++) {
            const int k0 = ks8 * 16;
            uint32_t bf[8][4];
            #pragma unroll
            for (int ni = 0; ni < 8; ni++)
                ldsm4(bf[ni], kAddr + (ni * 8 * AKLD + k0) * 4);
            #pragma unroll
            for (int hh = 0; hh < 2; hh++) {
                uint32_t af[4];
                ldsm4(af, qAddr + (k0 + 8 * hh) * 4);
                #pragma unroll
                for (int ni = 0; ni < 8; ni++)
                    mma_tf32(sc[ni], af, bf[ni][2*hh], bf[ni][2*hh + 1]);
            }
        }

        // ---- causal mask (diagonal tiles only)
        if (kt * 64 + 63 > qb * 128 + w16) {
            int qi0 = qb * 128 + w16 + g;
            #pragma unroll
            for (int ni = 0; ni < 8; ni++) {
                int ki = kt * 64 + ni * 8 + 2 * tig;
                if (ki     > qi0)     sc[ni][0] = -1e30f;
                if (ki + 1 > qi0)     sc[ni][1] = -1e30f;
                if (ki     > qi0 + 8) sc[ni][2] = -1e30f;
                if (ki + 1 > qi0 + 8) sc[ni][3] = -1e30f;
            }
        }

        // ---- online softmax (rows g and g+8, warp-local)
        float alpha[2];
        #pragma unroll
        for (int hh = 0; hh < 2; hh++) {
            float mx = -1e30f;
            #pragma unroll
            for (int ni = 0; ni < 8; ni++)
                mx = fmaxf(mx, fmaxf(sc[ni][2*hh], sc[ni][2*hh + 1]));
            mx = fmaxf(mx, __shfl_xor_sync(0xffffffffu, mx, 1));
            mx = fmaxf(mx, __shfl_xor_sync(0xffffffffu, mx, 2));
            float m_new = fmaxf(m_run[hh], mx);
            alpha[hh] = __expf(m_run[hh] - m_new);
            m_run[hh] = m_new;
            float rs = 0.f;
            #pragma unroll
            for (int ni = 0; ni < 8; ni++) {
                float p0 = __expf(sc[ni][2*hh]     - m_new);
                float p1 = __expf(sc[ni][2*hh + 1] - m_new);
                sc[ni][2*hh] = p0; sc[ni][2*hh + 1] = p1;
                rs += p0 + p1;
            }
            rs += __shfl_xor_sync(0xffffffffu, rs, 1);
            rs += __shfl_xor_sync(0xffffffffu, rs, 2);
            l_run[hh] = l_run[hh] * alpha[hh] + rs;
        }

        // ---- stage P (tf32) into warp-private smem rows
        #pragma unroll
        for (int ni = 0; ni < 8; ni++) {
            *reinterpret_cast<float2*>(&Ps[(w16 + g) * APLD + ni * 8 + 2 * tig]) =
                make_float2(f2tf32(sc[ni][0]), f2tf32(sc[ni][1]));
            *reinterpret_cast<float2*>(&Ps[(w16 + g + 8) * APLD + ni * 8 + 2 * tig]) =
                make_float2(f2tf32(sc[ni][2]), f2tf32(sc[ni][3]));
        }
        __syncwarp();

        // ---- O = alpha*O + P V
        #pragma unroll
        for (int ni = 0; ni < 16; ni++) {
            oacc[ni][0] *= alpha[0]; oacc[ni][1] *= alpha[0];
            oacc[ni][2] *= alpha[1]; oacc[ni][3] *= alpha[1];
        }
        uint32_t afP[8][4];
        #pragma unroll
        for (int ks = 0; ks < 8; ks++)
            ldsm4(afP[ks], pAddrA + ks * 8 * 4);
        #pragma unroll
        for (int ni = 0; ni < 16; ni++) {
            #pragma unroll
            for (int ks8 = 0; ks8 < 4; ks8++) {
                uint32_t bv[4];
                ldsm4(bv, vAddr + (ni * 8 * AVLD + ks8 * 16) * 4);
                mma_tf32(oacc[ni], afP[2*ks8],     bv[0], bv[1]);
                mma_tf32(oacc[ni], afP[2*ks8 + 1], bv[2], bv[3]);
            }
        }
    }

    // ---- epilogue: normalize, tf32-round (feeds Wo GEMM), store
    #pragma unroll
    for (int hh = 0; hh < 2; hh++) {
        float inv = 1.f / l_run[hh];
        int row = qb * 128 + w16 + g + 8 * hh;
        size_t base = (size_t)(b * SEQ + row) * EMB + h * HD;
        #pragma unroll
        for (int ni = 0; ni < 16; ni++) {
            int c = ni * 8 + 2 * tig;
            *reinterpret_cast<float2*>(&out[base + c]) =
                make_float2(f2tf32(oacc[ni][2*hh] * inv),
                            f2tf32(oacc[ni][2*hh + 1] * inv));
        }
    }
}

// ---------------------------------------------------------------------------
// Launch
// ---------------------------------------------------------------------------
extern "C" void kernel_launch(void* const* d_in, const int* in_sizes, int n_in,
                              void* d_out, int out_size)
{
    const float* x    = (const float*)d_in[0];
    const float* Wqkv = (const float*)d_in[1];
    const float* Wo   = (const float*)d_in[2];
    const float* fc   = (const float*)d_in[3];
    float* out        = (float*)d_out;

    float *qkv, *att, *xt, *wqkvt, *wot;
    cudaGetSymbolAddress((void**)&qkv,   g_qkv);
    cudaGetSymbolAddress((void**)&att,   g_att);
    cudaGetSymbolAddress((void**)&xt,    g_xt);
    cudaGetSymbolAddress((void**)&wqkvt, g_wqkvt);
    cudaGetSymbolAddress((void**)&wot,   g_wot);

    cudaFuncSetAttribute(attn_tc_kernel,
                         cudaFuncAttributeMaxDynamicSharedMemorySize,
                         ATT_SMEM_BYTES);
    cudaFuncSetAttribute(gemm_tf32_v2,
                         cudaFuncAttributeMaxDynamicSharedMemorySize,
                         GEMM_SMEM_BYTES);

    // 0) prep: round x to tf32; round+transpose weights to [N][K]
    {
        int n4 = (MROWS * EMB) / 4;
        cvt_tf32_kernel<<<(n4 + 255) / 256, 256>>>(x, xt, n4);
        dim3 b32(32, 8);
        transpose_tf32_kernel<<<dim3(QKV_N / 32, EMB / 32), b32>>>(Wqkv, wqkvt, EMB, QKV_N);
        transpose_tf32_kernel<<<dim3(EMB / 32,  EMB / 32), b32>>>(Wo,   wot,   EMB, EMB);
    }

    // 1) qkv = x @ Wqkv
    {
        dim3 grid(QKV_N / 128, MROWS / 128);
        gemm_tf32_v2<<<grid, 256, GEMM_SMEM_BYTES>>>(xt, wqkvt, qkv,
                                                     MROWS, QKV_N, EMB);
    }

    // 2) RoPE
    {
        int total  = BATCH * SEQ * 2 * NH * (HD / 2);
        rope_kernel<<<(total + 255) / 256, 256>>>(qkv, fc);
    }

    // 3) tensor-core causal flash attention
    {
        dim3 grid(SEQ / 128, BATCH * NH);
        attn_tc_kernel<<<grid, 256, ATT_SMEM_BYTES>>>(qkv, att);
    }

    // 4) out = att @ Wo
    {
        dim3 grid(EMB / 128, MROWS / 128);
        gemm_tf32_v2<<<grid, 256, GEMM_SMEM_BYTES>>>(att, wot, out,
                                                     MROWS, EMB, EMB);
    }
}